// round 1
// baseline (speedup 1.0000x reference)
#include <cuda_runtime.h>
#include <math.h>

#define N_MEM   500000
#define D_LAT   512
#define D_Q     768
#define CHUNK   2048
#define NB3     ((N_MEM + CHUNK - 1) / CHUNK)   // 245
#define NPART   (NB3 * 32)                      // 7840

__device__ __align__(16) float g_q[D_LAT];
__device__ __align__(16) float g_qn[D_LAT];
__device__ __align__(16) float g_aj[D_LAT];
__device__ __align__(16) float g_sims[N_MEM];
__device__ float g_part_v[NPART];
__device__ int   g_part_i[NPART];
__device__ int   g_cand[32];
__device__ float g_scores[32];

__device__ __forceinline__ float warp_sum(float v) {
#pragma unroll
    for (int o = 16; o; o >>= 1) v += __shfl_xor_sync(0xffffffffu, v, o);
    return v;
}

// ---------------------------------------------------------------------------
// 1) q = Wp @ query + bp ; qn = q / (||q|| + 1e-8)
// 512 threads = 16 warps, warp-per-row x 32 rows each
__global__ void k_proj(const float* __restrict__ query,
                       const float* __restrict__ Wp,
                       const float* __restrict__ bp) {
    __shared__ float qs[D_Q];
    __shared__ float qv[D_LAT];
    __shared__ float red[16];
    __shared__ float s_inv;
    int t = threadIdx.x;
    for (int i = t; i < D_Q; i += 512) qs[i] = query[i];
    __syncthreads();
    int w = t >> 5, lane = t & 31;
    float ss = 0.f;
    for (int rr = 0; rr < 32; rr++) {
        int r = w * 32 + rr;
        const float* row = Wp + (size_t)r * D_Q;
        float d = 0.f;
#pragma unroll
        for (int u = 0; u < 24; u++) d += row[lane + 32 * u] * qs[lane + 32 * u];
        d = warp_sum(d);
        if (lane == 0) { float v = d + bp[r]; qv[r] = v; ss += v * v; }
    }
    if (lane == 0) red[w] = ss;
    __syncthreads();
    if (t == 0) {
        float s = 0.f;
        for (int i = 0; i < 16; i++) s += red[i];
        s_inv = 1.0f / (sqrtf(s) + 1e-8f);
    }
    __syncthreads();
    for (int i = t; i < D_LAT; i += 512) {
        g_q[i]  = qv[i];
        g_qn[i] = qv[i] * s_inv;
    }
}

// ---------------------------------------------------------------------------
// 2) a_j = b1[j] + dot(q, W1[j, 0:512])  (query half of the rerank GEMM,
//    shared by all candidates). 512 threads, warp-per-j x 32.
__global__ void k_aj(const float* __restrict__ W1, const float* __restrict__ b1) {
    __shared__ float qsh[D_LAT];
    int t = threadIdx.x;
    for (int i = t; i < D_LAT; i += 512) qsh[i] = g_q[i];
    __syncthreads();
    int w = t >> 5, lane = t & 31;
    for (int jj = 0; jj < 32; jj++) {
        int j = w * 32 + jj;
        const float* row = W1 + (size_t)j * (2 * D_LAT);
        float d = 0.f;
#pragma unroll
        for (int u = 0; u < 16; u++) d += row[lane + 32 * u] * qsh[lane + 32 * u];
        d = warp_sum(d);
        if (lane == 0) g_aj[j] = d + b1[j];
    }
}

// ---------------------------------------------------------------------------
// 3) sims[i] = dot(mem_i, qn) / (||mem_i|| + 1e-8)  — single fused HBM pass.
// warp-per-row, 8 rows/block, float4 loads.
__global__ void k_sims(const float* __restrict__ mem) {
    __shared__ float4 qsh[D_LAT / 4];
    int t = threadIdx.x;
    if (t < D_LAT / 4) qsh[t] = ((const float4*)g_qn)[t];
    __syncthreads();
    int row = blockIdx.x * 8 + (t >> 5);
    int lane = t & 31;
    const float4* r4 = (const float4*)(mem + (size_t)row * D_LAT);
    float d = 0.f, ss = 0.f;
#pragma unroll
    for (int u = 0; u < 4; u++) {
        float4 v = r4[lane + 32 * u];
        float4 q = qsh[lane + 32 * u];
        d  += v.x * q.x + v.y * q.y + v.z * q.z + v.w * q.w;
        ss += v.x * v.x + v.y * v.y + v.z * v.z + v.w * v.w;
    }
    d = warp_sum(d);
    ss = warp_sum(ss);
    if (lane == 0) g_sims[row] = d / (sqrtf(ss) + 1e-8f);
}

// ---------------------------------------------------------------------------
// 4a) per-chunk top-32: block b selects top-32 of sims[b*CHUNK .. ) via 32
// argmax rounds over an smem copy. Lower-index wins ties (top_k stability).
__global__ void k_top32a() {
    __shared__ float sv[CHUNK];
    __shared__ float bw[8];
    __shared__ int   bidx_s[8];
    __shared__ int   bpos_s[8];
    int t = threadIdx.x;               // 256
    int base = blockIdx.x * CHUNK;
    for (int i = t; i < CHUNK; i += 256) {
        int gi = base + i;
        sv[i] = (gi < N_MEM) ? g_sims[gi] : -1e30f;
    }
    __syncthreads();
    int w = t >> 5, lane = t & 31;
    for (int r = 0; r < 32; r++) {
        float bv = -1e30f; int bi = 0x7fffffff; int bp = -1;
        for (int i = t; i < CHUNK; i += 256) {
            float v = sv[i];
            if (v > bv || (v == bv && i < bp)) { bv = v; bi = base + i; bp = i; }
        }
#pragma unroll
        for (int o = 16; o; o >>= 1) {
            float ov = __shfl_xor_sync(0xffffffffu, bv, o);
            int   oi = __shfl_xor_sync(0xffffffffu, bi, o);
            int   op = __shfl_xor_sync(0xffffffffu, bp, o);
            if (ov > bv || (ov == bv && oi < bi)) { bv = ov; bi = oi; bp = op; }
        }
        if (lane == 0) { bw[w] = bv; bidx_s[w] = bi; bpos_s[w] = bp; }
        __syncthreads();
        if (t == 0) {
            float fv = bw[0]; int fi = bidx_s[0]; int fp = bpos_s[0];
            for (int k = 1; k < 8; k++)
                if (bw[k] > fv || (bw[k] == fv && bidx_s[k] < fi)) { fv = bw[k]; fi = bidx_s[k]; fp = bpos_s[k]; }
            g_part_v[blockIdx.x * 32 + r] = fv;
            g_part_i[blockIdx.x * 32 + r] = fi;
            sv[fp] = -1e30f;
        }
        __syncthreads();
    }
}

// 4b) merge 245*32 partial candidates -> global top-32 (descending).
__global__ void k_top32b() {
    __shared__ float bw[8];
    __shared__ int   bidx_s[8];
    __shared__ int   bpos_s[8];
    int t = threadIdx.x;   // 256
    int w = t >> 5, lane = t & 31;
    for (int r = 0; r < 32; r++) {
        float bv = -1e30f; int bi = 0x7fffffff; int bp = -1;
        for (int j = t; j < NPART; j += 256) {
            float v = g_part_v[j];
            int  idx = g_part_i[j];
            if (v > bv || (v == bv && idx < bi)) { bv = v; bi = idx; bp = j; }
        }
#pragma unroll
        for (int o = 16; o; o >>= 1) {
            float ov = __shfl_xor_sync(0xffffffffu, bv, o);
            int   oi = __shfl_xor_sync(0xffffffffu, bi, o);
            int   op = __shfl_xor_sync(0xffffffffu, bp, o);
            if (ov > bv || (ov == bv && oi < bi)) { bv = ov; bi = oi; bp = op; }
        }
        if (lane == 0) { bw[w] = bv; bidx_s[w] = bi; bpos_s[w] = bp; }
        __syncthreads();
        if (t == 0) {
            float fv = bw[0]; int fi = bidx_s[0]; int fp = bpos_s[0];
            for (int k = 1; k < 8; k++)
                if (bw[k] > fv || (bw[k] == fv && bidx_s[k] < fi)) { fv = bw[k]; fi = bidx_s[k]; fp = bpos_s[k]; }
            g_cand[r] = fi;
            g_part_v[fp] = -1e30f;
        }
        __syncthreads();
    }
}

// ---------------------------------------------------------------------------
// 5) rerank: score[c] = b2 + sum_j relu(a_j + dot(cand_c, W1[j,512:1024])) * W2[j]
// 32 blocks (one per candidate), 8 warps, warp-per-j x 64.
__global__ void k_rerank(const float* __restrict__ mem,
                         const float* __restrict__ W1,
                         const float* __restrict__ W2,
                         const float* __restrict__ b2) {
    __shared__ float cs[D_LAT];
    __shared__ float wacc[8];
    int c = blockIdx.x, t = threadIdx.x;
    int cidx = g_cand[c];
    for (int i = t; i < D_LAT; i += 256) cs[i] = mem[(size_t)cidx * D_LAT + i];
    __syncthreads();
    int w = t >> 5, lane = t & 31;
    float acc = 0.f;
    for (int jj = 0; jj < 64; jj++) {
        int j = w * 64 + jj;
        const float* row = W1 + (size_t)j * (2 * D_LAT) + D_LAT;
        float d = 0.f;
#pragma unroll
        for (int u = 0; u < 16; u++) d += row[lane + 32 * u] * cs[lane + 32 * u];
        d = warp_sum(d);
        float h = g_aj[j] + d;
        if (h > 0.f) acc += h * W2[j];
    }
    if (lane == 0) wacc[w] = acc;
    __syncthreads();
    if (t == 0) {
        float s = 0.f;
        for (int i = 0; i < 8; i++) s += wacc[i];
        g_scores[c] = s + b2[0];
    }
}

// ---------------------------------------------------------------------------
// 6) top-16 of 32 by rerank score (stable desc), emit scores then indices.
__global__ void k_final(float* __restrict__ out, int out_size) {
    if (threadIdx.x == 0) {
        float sc[32]; int id[32];
        for (int i = 0; i < 32; i++) { sc[i] = g_scores[i]; id[i] = g_cand[i]; }
        for (int r = 0; r < 16; r++) {
            float bv = -1e30f; int bp = 0;
            for (int j = 0; j < 32; j++)
                if (sc[j] > bv) { bv = sc[j]; bp = j; }
            if (r < out_size)      out[r]      = bv;
            if (16 + r < out_size) out[16 + r] = (float)id[bp];
            sc[bp] = -1e30f;
        }
    }
}

// ---------------------------------------------------------------------------
extern "C" void kernel_launch(void* const* d_in, const int* in_sizes, int n_in,
                              void* d_out, int out_size) {
    const float* query  = (const float*)d_in[0];
    const float* memory = (const float*)d_in[1];
    const float* Wp     = (const float*)d_in[2];
    const float* bp     = (const float*)d_in[3];
    const float* W1     = (const float*)d_in[4];
    const float* b1     = (const float*)d_in[5];
    const float* W2     = (const float*)d_in[6];
    const float* b2     = (const float*)d_in[7];
    (void)in_sizes; (void)n_in;

    k_proj  <<<1, 512>>>(query, Wp, bp);
    k_aj    <<<1, 512>>>(W1, b1);
    k_sims  <<<N_MEM / 8, 256>>>(memory);
    k_top32a<<<NB3, 256>>>();
    k_top32b<<<1, 256>>>();
    k_rerank<<<32, 256>>>(memory, W1, W2, b2);
    k_final <<<1, 32>>>((float*)d_out, out_size);
}

// round 2
// speedup vs baseline: 1.8996x; 1.8996x over previous
#include <cuda_runtime.h>
#include <math.h>

#define N_MEM   500000
#define D_LAT   512
#define D_Q     768
#define NBINS   4096
#define CAP     4096
#define SIMS_GRID 592                       // 4 blocks/SM * 148
#define SIMS_WARPS (SIMS_GRID * 8)          // 4736
#define SIMS_STRIDE (SIMS_WARPS * 2)        // rows per grid-iteration

__device__ __align__(16) float g_q[D_LAT];
__device__ float g_ss_part[16];
__device__ __align__(16) float g_aj[D_LAT];
__device__ __align__(16) float g_sims[N_MEM];
__device__ unsigned g_hist[NBINS];
__device__ unsigned g_tkey;
__device__ int g_ncand;
__device__ float g_cv[CAP];
__device__ int   g_ci[CAP];
__device__ int   g_cand[32];
__device__ float g_scores[32];

__device__ __forceinline__ float warp_sum(float v) {
#pragma unroll
    for (int o = 16; o; o >>= 1) v += __shfl_xor_sync(0xffffffffu, v, o);
    return v;
}

// monotonic float->uint key: order-preserving over all floats
__device__ __forceinline__ unsigned mkey(float f) {
    unsigned u = __float_as_uint(f);
    return (u & 0x80000000u) ? ~u : (u | 0x80000000u);
}

// ---------------------------------------------------------------------------
// 1) q = Wp @ query + bp (row-parallel, 16 blocks x 512 thr, 2 rows/warp).
//    Writes g_q and per-block sum-of-squares (deterministic split-norm).
//    Also zeroes g_hist for this replay.
__global__ void __launch_bounds__(512) k_proj(const float* __restrict__ query,
                                              const float* __restrict__ Wp,
                                              const float* __restrict__ bp) {
    __shared__ float4 qs[D_Q / 4];
    __shared__ float red[16];
    int t = threadIdx.x, blk = blockIdx.x;
    int gt = blk * 512 + t;
    if (gt < NBINS) g_hist[gt] = 0;
    for (int i = t; i < D_Q / 4; i += 512) qs[i] = ((const float4*)query)[i];
    __syncthreads();
    int w = t >> 5, lane = t & 31;
    int r0 = blk * 32 + w * 2, r1 = r0 + 1;
    const float4* p0 = (const float4*)(Wp + (size_t)r0 * D_Q);
    const float4* p1 = (const float4*)(Wp + (size_t)r1 * D_Q);
    float d0 = 0.f, d1 = 0.f;
#pragma unroll
    for (int u = 0; u < 6; u++) {
        float4 a = p0[lane + 32 * u];
        float4 b = p1[lane + 32 * u];
        float4 q = qs[lane + 32 * u];
        d0 += a.x * q.x + a.y * q.y + a.z * q.z + a.w * q.w;
        d1 += b.x * q.x + b.y * q.y + b.z * q.z + b.w * q.w;
    }
    d0 = warp_sum(d0); d1 = warp_sum(d1);
    if (lane == 0) {
        float v0 = d0 + bp[r0], v1 = d1 + bp[r1];
        g_q[r0] = v0; g_q[r1] = v1;
        red[w] = v0 * v0 + v1 * v1;
    }
    __syncthreads();
    if (t == 0) {
        float s = 0.f;
        for (int i = 0; i < 16; i++) s += red[i];
        g_ss_part[blk] = s;
    }
}

// ---------------------------------------------------------------------------
// 2) a_j = b1[j] + dot(q, W1[j, 0:512]). 32 blocks x 256 thr, 2 j per warp.
__global__ void __launch_bounds__(256) k_aj(const float* __restrict__ W1,
                                            const float* __restrict__ b1) {
    __shared__ float4 qsh[D_LAT / 4];
    int t = threadIdx.x;
    for (int i = t; i < D_LAT / 4; i += 256) qsh[i] = ((const float4*)g_q)[i];
    __syncthreads();
    int w = t >> 5, lane = t & 31;
    int j0 = blockIdx.x * 16 + w * 2, j1 = j0 + 1;
    const float4* p0 = (const float4*)(W1 + (size_t)j0 * (2 * D_LAT));
    const float4* p1 = (const float4*)(W1 + (size_t)j1 * (2 * D_LAT));
    float d0 = 0.f, d1 = 0.f;
#pragma unroll
    for (int u = 0; u < 4; u++) {
        float4 a = p0[lane + 32 * u];
        float4 b = p1[lane + 32 * u];
        float4 q = qsh[lane + 32 * u];
        d0 += a.x * q.x + a.y * q.y + a.z * q.z + a.w * q.w;
        d1 += b.x * q.x + b.y * q.y + b.z * q.z + b.w * q.w;
    }
    d0 = warp_sum(d0); d1 = warp_sum(d1);
    if (lane == 0) { g_aj[j0] = d0 + b1[j0]; g_aj[j1] = d1 + b1[j1]; }
}

// ---------------------------------------------------------------------------
// 3) sims[i] = dot(mem_i, qn) / (||mem_i|| + 1e-8). Persistent, 2 rows/warp
//    per iter (8 outstanding LDG.128/thread). Fused smem histogram of
//    monotonic keys; nonzero bins flushed to g_hist.
__global__ void __launch_bounds__(256, 4) k_sims(const float* __restrict__ mem) {
    __shared__ float4 qsh[D_LAT / 4];
    __shared__ unsigned hist[NBINS];
    int t = threadIdx.x;
    float ss = 0.f;
#pragma unroll
    for (int i = 0; i < 16; i++) ss += g_ss_part[i];
    float inv = 1.0f / (sqrtf(ss) + 1e-8f);
    for (int i = t; i < D_LAT / 4; i += 256) {
        float4 q = ((const float4*)g_q)[i];
        q.x *= inv; q.y *= inv; q.z *= inv; q.w *= inv;
        qsh[i] = q;
    }
    for (int i = t; i < NBINS; i += 256) hist[i] = 0;
    __syncthreads();
    int w = t >> 5, lane = t & 31;
    int wg = blockIdx.x * 8 + w;
    for (int base = wg * 2; base < N_MEM; base += SIMS_STRIDE) {
        const float4* r0 = (const float4*)(mem + (size_t)base * D_LAT);
        const float4* r1 = (const float4*)(mem + (size_t)(base + 1) * D_LAT);
        float d0 = 0.f, s0 = 0.f, d1 = 0.f, s1 = 0.f;
#pragma unroll
        for (int u = 0; u < 4; u++) {
            float4 a = r0[lane + 32 * u];
            float4 b = r1[lane + 32 * u];
            float4 q = qsh[lane + 32 * u];
            d0 += a.x * q.x + a.y * q.y + a.z * q.z + a.w * q.w;
            s0 += a.x * a.x + a.y * a.y + a.z * a.z + a.w * a.w;
            d1 += b.x * q.x + b.y * q.y + b.z * q.z + b.w * q.w;
            s1 += b.x * b.x + b.y * b.y + b.z * b.z + b.w * b.w;
        }
        d0 = warp_sum(d0); s0 = warp_sum(s0);
        d1 = warp_sum(d1); s1 = warp_sum(s1);
        if (lane == 0) {
            float v0 = d0 / (sqrtf(s0) + 1e-8f);
            float v1 = d1 / (sqrtf(s1) + 1e-8f);
            g_sims[base] = v0;
            g_sims[base + 1] = v1;
            atomicAdd(&hist[mkey(v0) >> 20], 1u);
            atomicAdd(&hist[mkey(v1) >> 20], 1u);
        }
    }
    __syncthreads();
    for (int i = t; i < NBINS; i += 256) {
        unsigned c = hist[i];
        if (c) atomicAdd(&g_hist[i], c);
    }
}

// ---------------------------------------------------------------------------
// 4) find threshold bin: smallest bin b with count(key >= b<<20) >= 32.
__global__ void k_thresh() {
    __shared__ unsigned part[256];
    int t = threadIdx.x;
    unsigned s = 0;
#pragma unroll
    for (int i = 0; i < 16; i++) s += g_hist[t * 16 + i];
    part[t] = s;
    __syncthreads();
    if (t == 0) {
        unsigned cum = 0;
        int seg = 255;
        for (; seg > 0; seg--) {
            if (cum + part[seg] >= 32u) break;
            cum += part[seg];
        }
        int bin = seg * 16 + 15;
        for (; bin > seg * 16; bin--) {
            cum += g_hist[bin];
            if (cum >= 32u) break;
        }
        g_tkey = ((unsigned)bin) << 20;
        g_ncand = 0;
    }
}

// ---------------------------------------------------------------------------
// 5) compact all sims with key >= threshold (expected ~50 survivors).
__global__ void __launch_bounds__(256) k_filter() {
    unsigned tkey = g_tkey;
    int i4 = blockIdx.x * blockDim.x + threadIdx.x;
    int stride = gridDim.x * blockDim.x;
    for (; i4 < N_MEM / 4; i4 += stride) {
        float4 v = ((const float4*)g_sims)[i4];
        int i = i4 * 4;
        if (mkey(v.x) >= tkey) { int p = atomicAdd(&g_ncand, 1); if (p < CAP) { g_cv[p] = v.x; g_ci[p] = i; } }
        if (mkey(v.y) >= tkey) { int p = atomicAdd(&g_ncand, 1); if (p < CAP) { g_cv[p] = v.y; g_ci[p] = i + 1; } }
        if (mkey(v.z) >= tkey) { int p = atomicAdd(&g_ncand, 1); if (p < CAP) { g_cv[p] = v.z; g_ci[p] = i + 2; } }
        if (mkey(v.w) >= tkey) { int p = atomicAdd(&g_ncand, 1); if (p < CAP) { g_cv[p] = v.w; g_ci[p] = i + 3; } }
    }
}

// ---------------------------------------------------------------------------
// 6) exact stable top-32 of the compacted candidates (value desc, index asc).
__global__ void k_select() {
    __shared__ float bw[8];
    __shared__ int bi_s[8], bp_s[8];
    int t = threadIdx.x, w = t >> 5, lane = t & 31;
    int n = g_ncand; if (n > CAP) n = CAP;
    for (int r = 0; r < 32; r++) {
        float bv = -1e30f; int bi = 0x7fffffff, bp = -1;
        for (int i = t; i < n; i += 256) {
            float v = g_cv[i]; int idx = g_ci[i];
            if (v > bv || (v == bv && idx < bi)) { bv = v; bi = idx; bp = i; }
        }
#pragma unroll
        for (int o = 16; o; o >>= 1) {
            float ov = __shfl_xor_sync(0xffffffffu, bv, o);
            int oi = __shfl_xor_sync(0xffffffffu, bi, o);
            int op = __shfl_xor_sync(0xffffffffu, bp, o);
            if (ov > bv || (ov == bv && oi < bi)) { bv = ov; bi = oi; bp = op; }
        }
        if (lane == 0) { bw[w] = bv; bi_s[w] = bi; bp_s[w] = bp; }
        __syncthreads();
        if (t == 0) {
            float fv = bw[0]; int fi = bi_s[0], fp = bp_s[0];
            for (int k = 1; k < 8; k++)
                if (bw[k] > fv || (bw[k] == fv && bi_s[k] < fi)) { fv = bw[k]; fi = bi_s[k]; fp = bp_s[k]; }
            g_cand[r] = fi;
            if (fp >= 0) g_cv[fp] = -1e30f;
        }
        __syncthreads();
    }
}

// ---------------------------------------------------------------------------
// 7) rerank: score[c] = b2 + sum_j relu(a_j + dot(cand_c, W1[j,512:])) * W2[j]
//    32 blocks x 512 thr (16 warps), 2 j-rows interleaved per iter.
__global__ void __launch_bounds__(512) k_rerank(const float* __restrict__ mem,
                                                const float* __restrict__ W1,
                                                const float* __restrict__ W2,
                                                const float* __restrict__ b2) {
    __shared__ float4 cs[D_LAT / 4];
    __shared__ float wacc[16];
    int c = blockIdx.x, t = threadIdx.x;
    int cidx = g_cand[c];
    for (int i = t; i < D_LAT / 4; i += 512)
        cs[i] = ((const float4*)(mem + (size_t)cidx * D_LAT))[i];
    __syncthreads();
    int w = t >> 5, lane = t & 31;
    float acc = 0.f;
    for (int jj = 0; jj < 32; jj += 2) {
        int j0 = w * 32 + jj, j1 = j0 + 1;
        const float4* p0 = (const float4*)(W1 + (size_t)j0 * (2 * D_LAT) + D_LAT);
        const float4* p1 = (const float4*)(W1 + (size_t)j1 * (2 * D_LAT) + D_LAT);
        float d0 = 0.f, d1 = 0.f;
#pragma unroll
        for (int u = 0; u < 4; u++) {
            float4 a = p0[lane + 32 * u];
            float4 b = p1[lane + 32 * u];
            float4 q = cs[lane + 32 * u];
            d0 += a.x * q.x + a.y * q.y + a.z * q.z + a.w * q.w;
            d1 += b.x * q.x + b.y * q.y + b.z * q.z + b.w * q.w;
        }
        d0 = warp_sum(d0); d1 = warp_sum(d1);
        if (lane == 0) {
            float h0 = g_aj[j0] + d0; if (h0 > 0.f) acc += h0 * W2[j0];
            float h1 = g_aj[j1] + d1; if (h1 > 0.f) acc += h1 * W2[j1];
        }
    }
    if (lane == 0) wacc[w] = acc;
    __syncthreads();
    if (t == 0) {
        float s = 0.f;
        for (int i = 0; i < 16; i++) s += wacc[i];
        g_scores[c] = s + b2[0];
    }
}

// ---------------------------------------------------------------------------
// 8) top-16 of 32 by rerank score (stable desc): scores then indices.
__global__ void k_final(float* __restrict__ out, int out_size) {
    if (threadIdx.x == 0) {
        float sc[32]; int id[32];
        for (int i = 0; i < 32; i++) { sc[i] = g_scores[i]; id[i] = g_cand[i]; }
        for (int r = 0; r < 16; r++) {
            float bv = -1e30f; int bp = 0;
            for (int j = 0; j < 32; j++)
                if (sc[j] > bv) { bv = sc[j]; bp = j; }
            if (r < out_size)      out[r]      = bv;
            if (16 + r < out_size) out[16 + r] = (float)id[bp];
            sc[bp] = -1e30f;
        }
    }
}

// ---------------------------------------------------------------------------
extern "C" void kernel_launch(void* const* d_in, const int* in_sizes, int n_in,
                              void* d_out, int out_size) {
    const float* query  = (const float*)d_in[0];
    const float* memory = (const float*)d_in[1];
    const float* Wp     = (const float*)d_in[2];
    const float* bp     = (const float*)d_in[3];
    const float* W1     = (const float*)d_in[4];
    const float* b1     = (const float*)d_in[5];
    const float* W2     = (const float*)d_in[6];
    const float* b2     = (const float*)d_in[7];
    (void)in_sizes; (void)n_in;

    k_proj  <<<16, 512>>>(query, Wp, bp);
    k_aj    <<<32, 256>>>(W1, b1);
    k_sims  <<<SIMS_GRID, 256>>>(memory);
    k_thresh<<<1, 256>>>();
    k_filter<<<512, 256>>>();
    k_select<<<1, 256>>>();
    k_rerank<<<32, 512>>>(memory, W1, W2, b2);
    k_final <<<1, 32>>>((float*)d_out, out_size);
}

// round 3
// speedup vs baseline: 1.9437x; 1.0232x over previous
#include <cuda_runtime.h>
#include <math.h>

#define N_MEM   500000
#define D_LAT   512
#define D_Q     768
#define NBINS   4096
#define CAP     4096
#define SIMS_GRID 592                       // 4 blocks/SM * 148
#define SIMS_WARPS (SIMS_GRID * 8)          // 4736
#define SIMS_STRIDE (SIMS_WARPS * 2)        // rows per grid-iteration
#define FILT_GRID 512

__device__ __align__(16) float g_q[D_LAT];
__device__ float g_ss_part[16];
__device__ __align__(16) float g_aj[D_LAT];
__device__ __align__(16) float g_sims[N_MEM];
__device__ unsigned g_hist[NBINS];
__device__ unsigned g_tkey;
__device__ int g_ncand;
__device__ float g_cv[CAP];
__device__ int   g_ci[CAP];
__device__ int   g_cand[32];
__device__ float g_scores[32];
__device__ int g_tick1, g_tick2, g_tick3;

__device__ __forceinline__ float warp_sum(float v) {
#pragma unroll
    for (int o = 16; o; o >>= 1) v += __shfl_xor_sync(0xffffffffu, v, o);
    return v;
}

// monotonic float->uint key: order-preserving over all floats
__device__ __forceinline__ unsigned mkey(float f) {
    unsigned u = __float_as_uint(f);
    return (u & 0x80000000u) ? ~u : (u | 0x80000000u);
}

// ---------------------------------------------------------------------------
// 1) q = Wp @ query + bp (16 blocks x 512 thr, 2 rows/warp). Also resets
//    g_hist / counters for this replay (graph-replay safe).
__global__ void __launch_bounds__(512) k_proj(const float* __restrict__ query,
                                              const float* __restrict__ Wp,
                                              const float* __restrict__ bp) {
    __shared__ float4 qs[D_Q / 4];
    __shared__ float red[16];
    int t = threadIdx.x, blk = blockIdx.x;
    int gt = blk * 512 + t;
    if (gt < NBINS) g_hist[gt] = 0;
    if (gt == 0) { g_ncand = 0; g_tick1 = 0; g_tick2 = 0; g_tick3 = 0; }
    for (int i = t; i < D_Q / 4; i += 512) qs[i] = ((const float4*)query)[i];
    __syncthreads();
    int w = t >> 5, lane = t & 31;
    int r0 = blk * 32 + w * 2, r1 = r0 + 1;
    const float4* p0 = (const float4*)(Wp + (size_t)r0 * D_Q);
    const float4* p1 = (const float4*)(Wp + (size_t)r1 * D_Q);
    float d0 = 0.f, d1 = 0.f;
#pragma unroll
    for (int u = 0; u < 6; u++) {
        float4 a = p0[lane + 32 * u];
        float4 b = p1[lane + 32 * u];
        float4 q = qs[lane + 32 * u];
        d0 += a.x * q.x + a.y * q.y + a.z * q.z + a.w * q.w;
        d1 += b.x * q.x + b.y * q.y + b.z * q.z + b.w * q.w;
    }
    d0 = warp_sum(d0); d1 = warp_sum(d1);
    if (lane == 0) {
        float v0 = d0 + bp[r0], v1 = d1 + bp[r1];
        g_q[r0] = v0; g_q[r1] = v1;
        red[w] = v0 * v0 + v1 * v1;
    }
    __syncthreads();
    if (t == 0) {
        float s = 0.f;
        for (int i = 0; i < 16; i++) s += red[i];
        g_ss_part[blk] = s;
    }
}

// ---------------------------------------------------------------------------
// 2) a_j = b1[j] + dot(q, W1[j, 0:512]). 32 blocks x 256 thr, 2 j per warp.
__global__ void __launch_bounds__(256) k_aj(const float* __restrict__ W1,
                                            const float* __restrict__ b1) {
    __shared__ float4 qsh[D_LAT / 4];
    int t = threadIdx.x;
    for (int i = t; i < D_LAT / 4; i += 256) qsh[i] = ((const float4*)g_q)[i];
    __syncthreads();
    int w = t >> 5, lane = t & 31;
    int j0 = blockIdx.x * 16 + w * 2, j1 = j0 + 1;
    const float4* p0 = (const float4*)(W1 + (size_t)j0 * (2 * D_LAT));
    const float4* p1 = (const float4*)(W1 + (size_t)j1 * (2 * D_LAT));
    float d0 = 0.f, d1 = 0.f;
#pragma unroll
    for (int u = 0; u < 4; u++) {
        float4 a = p0[lane + 32 * u];
        float4 b = p1[lane + 32 * u];
        float4 q = qsh[lane + 32 * u];
        d0 += a.x * q.x + a.y * q.y + a.z * q.z + a.w * q.w;
        d1 += b.x * q.x + b.y * q.y + b.z * q.z + b.w * q.w;
    }
    d0 = warp_sum(d0); d1 = warp_sum(d1);
    if (lane == 0) { g_aj[j0] = d0 + b1[j0]; g_aj[j1] = d1 + b1[j1]; }
}

// ---------------------------------------------------------------------------
// 3) sims[i] = dot(mem_i, qn)/(||mem_i||+1e-8). Persistent, 2 rows/warp/iter.
//    Fused smem histogram of monotonic keys. LAST block computes the
//    threshold key (warp-ballot suffix scan) — replaces the old k_thresh.
__global__ void __launch_bounds__(256, 4) k_sims(const float* __restrict__ mem) {
    __shared__ float4 qsh[D_LAT / 4];
    __shared__ unsigned hist[NBINS];
    __shared__ unsigned part[256];
    __shared__ int is_last;
    int t = threadIdx.x;
    float ss = 0.f;
#pragma unroll
    for (int i = 0; i < 16; i++) ss += g_ss_part[i];
    float inv = 1.0f / (sqrtf(ss) + 1e-8f);
    for (int i = t; i < D_LAT / 4; i += 256) {
        float4 q = ((const float4*)g_q)[i];
        q.x *= inv; q.y *= inv; q.z *= inv; q.w *= inv;
        qsh[i] = q;
    }
    for (int i = t; i < NBINS; i += 256) hist[i] = 0;
    __syncthreads();
    int w = t >> 5, lane = t & 31;
    int wg = blockIdx.x * 8 + w;
    for (int base = wg * 2; base < N_MEM; base += SIMS_STRIDE) {
        const float4* r0 = (const float4*)(mem + (size_t)base * D_LAT);
        const float4* r1 = (const float4*)(mem + (size_t)(base + 1) * D_LAT);
        float d0 = 0.f, s0 = 0.f, d1 = 0.f, s1 = 0.f;
#pragma unroll
        for (int u = 0; u < 4; u++) {
            float4 a = r0[lane + 32 * u];
            float4 b = r1[lane + 32 * u];
            float4 q = qsh[lane + 32 * u];
            d0 += a.x * q.x + a.y * q.y + a.z * q.z + a.w * q.w;
            s0 += a.x * a.x + a.y * a.y + a.z * a.z + a.w * a.w;
            d1 += b.x * q.x + b.y * q.y + b.z * q.z + b.w * q.w;
            s1 += b.x * b.x + b.y * b.y + b.z * b.z + b.w * b.w;
        }
        d0 = warp_sum(d0); s0 = warp_sum(s0);
        d1 = warp_sum(d1); s1 = warp_sum(s1);
        if (lane == 0) {
            float v0 = d0 / (sqrtf(s0) + 1e-8f);
            float v1 = d1 / (sqrtf(s1) + 1e-8f);
            g_sims[base] = v0;
            g_sims[base + 1] = v1;
            atomicAdd(&hist[mkey(v0) >> 20], 1u);
            atomicAdd(&hist[mkey(v1) >> 20], 1u);
        }
    }
    __syncthreads();
    for (int i = t; i < NBINS; i += 256) {
        unsigned c = hist[i];
        if (c) atomicAdd(&g_hist[i], c);
    }
    __syncthreads();
    if (t == 0) {
        __threadfence();
        is_last = (atomicAdd(&g_tick1, 1) == SIMS_GRID - 1);
    }
    __syncthreads();
    if (!is_last) return;

    // --- threshold epilogue (only last block) ---
    unsigned s16 = 0;
#pragma unroll
    for (int i = 0; i < 16; i++) s16 += g_hist[t * 16 + i];
    part[t] = s16;
    __syncthreads();
    if (w == 0) {
        unsigned c8 = 0;
#pragma unroll
        for (int i = 0; i < 8; i++) c8 += part[lane * 8 + i];
        unsigned suf = c8;
#pragma unroll
        for (int o = 1; o < 32; o <<= 1) {
            unsigned x = __shfl_down_sync(0xffffffffu, suf, o);
            if (lane + o < 32) suf += x;
        }
        unsigned above = __shfl_down_sync(0xffffffffu, suf, 1);
        if (lane == 31) above = 0;
        unsigned mask = __ballot_sync(0xffffffffu, suf >= 32u);
        int Lstar = 31 - __clz(mask);   // highest lane whose suffix >= 32
        if (lane == Lstar) {
            unsigned cum = above;
            int seg = Lstar * 8 + 7;
            for (; seg > Lstar * 8; seg--) {
                if (cum + part[seg] >= 32u) break;
                cum += part[seg];
            }
            int bin = seg * 16 + 15;
            for (; bin > seg * 16; bin--) {
                cum += g_hist[bin];
                if (cum >= 32u) break;
            }
            g_tkey = ((unsigned)bin) << 20;
        }
    }
}

// ---------------------------------------------------------------------------
// 5) compact sims with key >= threshold; LAST block runs the exact stable
//    top-32 select (value desc, index asc) — replaces k_select.
__global__ void __launch_bounds__(256) k_filter() {
    __shared__ float bw[8];
    __shared__ int bi_s[8], bp_s[8];
    __shared__ int is_last;
    unsigned tkey = g_tkey;
    int t = threadIdx.x;
    int i4 = blockIdx.x * 256 + t;
    for (; i4 < N_MEM / 4; i4 += FILT_GRID * 256) {
        float4 v = ((const float4*)g_sims)[i4];
        int i = i4 * 4;
        if (mkey(v.x) >= tkey) { int p = atomicAdd(&g_ncand, 1); if (p < CAP) { g_cv[p] = v.x; g_ci[p] = i; } }
        if (mkey(v.y) >= tkey) { int p = atomicAdd(&g_ncand, 1); if (p < CAP) { g_cv[p] = v.y; g_ci[p] = i + 1; } }
        if (mkey(v.z) >= tkey) { int p = atomicAdd(&g_ncand, 1); if (p < CAP) { g_cv[p] = v.z; g_ci[p] = i + 2; } }
        if (mkey(v.w) >= tkey) { int p = atomicAdd(&g_ncand, 1); if (p < CAP) { g_cv[p] = v.w; g_ci[p] = i + 3; } }
    }
    if (t == 0) {
        __threadfence();
        is_last = (atomicAdd(&g_tick2, 1) == FILT_GRID - 1);
    }
    __syncthreads();
    if (!is_last) return;

    // --- select epilogue (only last block) ---
    int w = t >> 5, lane = t & 31;
    int n = g_ncand; if (n > CAP) n = CAP;
    for (int r = 0; r < 32; r++) {
        float bv = -1e30f; int bi = 0x7fffffff, bp = -1;
        for (int i = t; i < n; i += 256) {
            float v = g_cv[i]; int idx = g_ci[i];
            if (v > bv || (v == bv && idx < bi)) { bv = v; bi = idx; bp = i; }
        }
#pragma unroll
        for (int o = 16; o; o >>= 1) {
            float ov = __shfl_xor_sync(0xffffffffu, bv, o);
            int oi = __shfl_xor_sync(0xffffffffu, bi, o);
            int op = __shfl_xor_sync(0xffffffffu, bp, o);
            if (ov > bv || (ov == bv && oi < bi)) { bv = ov; bi = oi; bp = op; }
        }
        if (lane == 0) { bw[w] = bv; bi_s[w] = bi; bp_s[w] = bp; }
        __syncthreads();
        if (t == 0) {
            float fv = bw[0]; int fi = bi_s[0], fp = bp_s[0];
            for (int k = 1; k < 8; k++)
                if (bw[k] > fv || (bw[k] == fv && bi_s[k] < fi)) { fv = bw[k]; fi = bi_s[k]; fp = bp_s[k]; }
            g_cand[r] = fi;
            if (fp >= 0) g_cv[fp] = -1e30f;
        }
        __syncthreads();
    }
}

// ---------------------------------------------------------------------------
// 7) rerank: score[c] = b2 + sum_j relu(a_j + dot(cand_c, W1[j,512:])) * W2[j]
//    32 blocks x 512 thr. LAST block runs the final top-16 and writes d_out.
__global__ void __launch_bounds__(512) k_rerank(const float* __restrict__ mem,
                                                const float* __restrict__ W1,
                                                const float* __restrict__ W2,
                                                const float* __restrict__ b2,
                                                float* __restrict__ out,
                                                int out_size) {
    __shared__ float4 cs[D_LAT / 4];
    __shared__ float wacc[16];
    __shared__ int is_last;
    int c = blockIdx.x, t = threadIdx.x;
    int cidx = g_cand[c];
    for (int i = t; i < D_LAT / 4; i += 512)
        cs[i] = ((const float4*)(mem + (size_t)cidx * D_LAT))[i];
    __syncthreads();
    int w = t >> 5, lane = t & 31;
    float acc = 0.f;
    for (int jj = 0; jj < 32; jj += 2) {
        int j0 = w * 32 + jj, j1 = j0 + 1;
        const float4* p0 = (const float4*)(W1 + (size_t)j0 * (2 * D_LAT) + D_LAT);
        const float4* p1 = (const float4*)(W1 + (size_t)j1 * (2 * D_LAT) + D_LAT);
        float d0 = 0.f, d1 = 0.f;
#pragma unroll
        for (int u = 0; u < 4; u++) {
            float4 a = p0[lane + 32 * u];
            float4 b = p1[lane + 32 * u];
            float4 q = cs[lane + 32 * u];
            d0 += a.x * q.x + a.y * q.y + a.z * q.z + a.w * q.w;
            d1 += b.x * q.x + b.y * q.y + b.z * q.z + b.w * q.w;
        }
        d0 = warp_sum(d0); d1 = warp_sum(d1);
        if (lane == 0) {
            float h0 = g_aj[j0] + d0; if (h0 > 0.f) acc += h0 * W2[j0];
            float h1 = g_aj[j1] + d1; if (h1 > 0.f) acc += h1 * W2[j1];
        }
    }
    if (lane == 0) wacc[w] = acc;
    __syncthreads();
    if (t == 0) {
        float s = 0.f;
        for (int i = 0; i < 16; i++) s += wacc[i];
        g_scores[c] = s + b2[0];
        __threadfence();
        is_last = (atomicAdd(&g_tick3, 1) == 31);
    }
    __syncthreads();
    if (!is_last) return;

    // --- final epilogue (only last block, thread 0) ---
    if (t == 0) {
        float sc[32]; int id[32];
        for (int i = 0; i < 32; i++) { sc[i] = g_scores[i]; id[i] = g_cand[i]; }
        for (int r = 0; r < 16; r++) {
            float bv = -1e30f; int bp = 0;
            for (int j = 0; j < 32; j++)
                if (sc[j] > bv) { bv = sc[j]; bp = j; }
            if (r < out_size)      out[r]      = bv;
            if (16 + r < out_size) out[16 + r] = (float)id[bp];
            sc[bp] = -1e30f;
        }
    }
}

// ---------------------------------------------------------------------------
extern "C" void kernel_launch(void* const* d_in, const int* in_sizes, int n_in,
                              void* d_out, int out_size) {
    const float* query  = (const float*)d_in[0];
    const float* memory = (const float*)d_in[1];
    const float* Wp     = (const float*)d_in[2];
    const float* bp     = (const float*)d_in[3];
    const float* W1     = (const float*)d_in[4];
    const float* b1     = (const float*)d_in[5];
    const float* W2     = (const float*)d_in[6];
    const float* b2     = (const float*)d_in[7];
    (void)in_sizes; (void)n_in;

    k_proj  <<<16, 512>>>(query, Wp, bp);
    k_aj    <<<32, 256>>>(W1, b1);
    k_sims  <<<SIMS_GRID, 256>>>(memory);
    k_filter<<<FILT_GRID, 256>>>();
    k_rerank<<<32, 512>>>(memory, W1, W2, b2, (float*)d_out, out_size);
}

// round 4
// speedup vs baseline: 1.9862x; 1.0219x over previous
#include <cuda_runtime.h>
#include <math.h>

#define N_MEM   500000
#define D_LAT   512
#define D_Q     768
#define NBINS   4096
#define CAP     1024
#define SIMS_GRID 592                       // 4 blocks/SM * 148
#define SIMS_WARPS (SIMS_GRID * 8)          // 4736
#define SIMS_STRIDE (SIMS_WARPS * 2)        // rows per grid-iteration
#define FILT_GRID 512

__device__ __align__(16) float g_q[D_LAT];
__device__ float g_ss_part[16];
__device__ __align__(16) float g_aj[D_LAT];
__device__ __align__(16) float g_sims[N_MEM];
__device__ unsigned g_hist[NBINS];
__device__ unsigned g_tkey;
__device__ int g_ncand;
__device__ float g_cv[CAP];
__device__ int   g_ci[CAP];
__device__ int   g_cand[32];
__device__ float g_scores[32];
__device__ int g_tick1, g_tick2, g_tick3;

__device__ __forceinline__ float warp_sum(float v) {
#pragma unroll
    for (int o = 16; o; o >>= 1) v += __shfl_xor_sync(0xffffffffu, v, o);
    return v;
}

// monotonic float->uint key: order-preserving over all floats
__device__ __forceinline__ unsigned mkey(float f) {
    unsigned u = __float_as_uint(f);
    return (u & 0x80000000u) ? ~u : (u | 0x80000000u);
}

// ---------------------------------------------------------------------------
// 1) q = Wp @ query + bp (16 blocks x 512 thr, 2 rows/warp). Also resets
//    g_hist / counters for this replay (graph-replay safe).
__global__ void __launch_bounds__(512) k_proj(const float* __restrict__ query,
                                              const float* __restrict__ Wp,
                                              const float* __restrict__ bp) {
    __shared__ float4 qs[D_Q / 4];
    __shared__ float red[16];
    int t = threadIdx.x, blk = blockIdx.x;
    int gt = blk * 512 + t;
    if (gt < NBINS) g_hist[gt] = 0;
    if (gt == 0) { g_ncand = 0; g_tick1 = 0; g_tick2 = 0; g_tick3 = 0; }
    for (int i = t; i < D_Q / 4; i += 512) qs[i] = ((const float4*)query)[i];
    __syncthreads();
    int w = t >> 5, lane = t & 31;
    int r0 = blk * 32 + w * 2, r1 = r0 + 1;
    const float4* p0 = (const float4*)(Wp + (size_t)r0 * D_Q);
    const float4* p1 = (const float4*)(Wp + (size_t)r1 * D_Q);
    float d0 = 0.f, d1 = 0.f;
#pragma unroll
    for (int u = 0; u < 6; u++) {
        float4 a = p0[lane + 32 * u];
        float4 b = p1[lane + 32 * u];
        float4 q = qs[lane + 32 * u];
        d0 += a.x * q.x + a.y * q.y + a.z * q.z + a.w * q.w;
        d1 += b.x * q.x + b.y * q.y + b.z * q.z + b.w * q.w;
    }
    d0 = warp_sum(d0); d1 = warp_sum(d1);
    if (lane == 0) {
        float v0 = d0 + bp[r0], v1 = d1 + bp[r1];
        g_q[r0] = v0; g_q[r1] = v1;
        red[w] = v0 * v0 + v1 * v1;
    }
    __syncthreads();
    if (t == 0) {
        float s = 0.f;
        for (int i = 0; i < 16; i++) s += red[i];
        g_ss_part[blk] = s;
    }
}

// ---------------------------------------------------------------------------
// 2) sims[i] = dot(mem_i, qn)/(||mem_i||+1e-8). Persistent, 2 rows/warp/iter.
//    Fused smem histogram of monotonic keys. LAST block computes the
//    threshold key (warp-ballot suffix scan).
__global__ void __launch_bounds__(256, 4) k_sims(const float* __restrict__ mem) {
    __shared__ float4 qsh[D_LAT / 4];
    __shared__ unsigned hist[NBINS];
    __shared__ unsigned part[256];
    __shared__ int is_last;
    int t = threadIdx.x;
    float ss = 0.f;
#pragma unroll
    for (int i = 0; i < 16; i++) ss += g_ss_part[i];
    float inv = 1.0f / (sqrtf(ss) + 1e-8f);
    for (int i = t; i < D_LAT / 4; i += 256) {
        float4 q = ((const float4*)g_q)[i];
        q.x *= inv; q.y *= inv; q.z *= inv; q.w *= inv;
        qsh[i] = q;
    }
    for (int i = t; i < NBINS; i += 256) hist[i] = 0;
    __syncthreads();
    int w = t >> 5, lane = t & 31;
    int wg = blockIdx.x * 8 + w;
    for (int base = wg * 2; base < N_MEM; base += SIMS_STRIDE) {
        const float4* r0 = (const float4*)(mem + (size_t)base * D_LAT);
        const float4* r1 = (const float4*)(mem + (size_t)(base + 1) * D_LAT);
        float d0 = 0.f, s0 = 0.f, d1 = 0.f, s1 = 0.f;
#pragma unroll
        for (int u = 0; u < 4; u++) {
            float4 a = r0[lane + 32 * u];
            float4 b = r1[lane + 32 * u];
            float4 q = qsh[lane + 32 * u];
            d0 += a.x * q.x + a.y * q.y + a.z * q.z + a.w * q.w;
            s0 += a.x * a.x + a.y * a.y + a.z * a.z + a.w * a.w;
            d1 += b.x * q.x + b.y * q.y + b.z * q.z + b.w * q.w;
            s1 += b.x * b.x + b.y * b.y + b.z * b.z + b.w * b.w;
        }
        d0 = warp_sum(d0); s0 = warp_sum(s0);
        d1 = warp_sum(d1); s1 = warp_sum(s1);
        if (lane == 0) {
            float v0 = d0 / (sqrtf(s0) + 1e-8f);
            float v1 = d1 / (sqrtf(s1) + 1e-8f);
            g_sims[base] = v0;
            g_sims[base + 1] = v1;
            atomicAdd(&hist[mkey(v0) >> 20], 1u);
            atomicAdd(&hist[mkey(v1) >> 20], 1u);
        }
    }
    __syncthreads();
    for (int i = t; i < NBINS; i += 256) {
        unsigned c = hist[i];
        if (c) atomicAdd(&g_hist[i], c);
    }
    __syncthreads();
    if (t == 0) {
        __threadfence();
        is_last = (atomicAdd(&g_tick1, 1) == SIMS_GRID - 1);
    }
    __syncthreads();
    if (!is_last) return;

    // --- threshold epilogue (only last block) ---
    unsigned s16 = 0;
#pragma unroll
    for (int i = 0; i < 16; i++) s16 += g_hist[t * 16 + i];
    part[t] = s16;
    __syncthreads();
    if (w == 0) {
        unsigned c8 = 0;
#pragma unroll
        for (int i = 0; i < 8; i++) c8 += part[lane * 8 + i];
        unsigned suf = c8;
#pragma unroll
        for (int o = 1; o < 32; o <<= 1) {
            unsigned x = __shfl_down_sync(0xffffffffu, suf, o);
            if (lane + o < 32) suf += x;
        }
        unsigned above = __shfl_down_sync(0xffffffffu, suf, 1);
        if (lane == 31) above = 0;
        unsigned mask = __ballot_sync(0xffffffffu, suf >= 32u);
        int Lstar = 31 - __clz(mask);   // highest lane whose suffix >= 32
        if (lane == Lstar) {
            unsigned cum = above;
            int seg = Lstar * 8 + 7;
            for (; seg > Lstar * 8; seg--) {
                if (cum + part[seg] >= 32u) break;
                cum += part[seg];
            }
            int bin = seg * 16 + 15;
            for (; bin > seg * 16; bin--) {
                cum += g_hist[bin];
                if (cum >= 32u) break;
            }
            g_tkey = ((unsigned)bin) << 20;
        }
    }
}

// ---------------------------------------------------------------------------
// 3) filter + aj + select.
//    Blocks 0..31 first compute a_j (16 j's each). All blocks compact sims
//    with key >= threshold. LAST block runs the exact stable top-32 select
//    over an smem copy with a single warp (no global latency per round).
__global__ void __launch_bounds__(256) k_filter(const float* __restrict__ W1,
                                                const float* __restrict__ b1) {
    __shared__ float sv[CAP];
    __shared__ int   si[CAP];
    __shared__ float4 qsh[D_LAT / 4];
    __shared__ int is_last;
    int t = threadIdx.x, blk = blockIdx.x;
    int w = t >> 5, lane = t & 31;

    // --- aj sub-task on blocks 0..31 ---
    if (blk < 32) {
        for (int i = t; i < D_LAT / 4; i += 256) qsh[i] = ((const float4*)g_q)[i];
        __syncthreads();
        int j0 = blk * 16 + w * 2, j1 = j0 + 1;
        const float4* p0 = (const float4*)(W1 + (size_t)j0 * (2 * D_LAT));
        const float4* p1 = (const float4*)(W1 + (size_t)j1 * (2 * D_LAT));
        float d0 = 0.f, d1 = 0.f;
#pragma unroll
        for (int u = 0; u < 4; u++) {
            float4 a = p0[lane + 32 * u];
            float4 b = p1[lane + 32 * u];
            float4 q = qsh[lane + 32 * u];
            d0 += a.x * q.x + a.y * q.y + a.z * q.z + a.w * q.w;
            d1 += b.x * q.x + b.y * q.y + b.z * q.z + b.w * q.w;
        }
        d0 = warp_sum(d0); d1 = warp_sum(d1);
        if (lane == 0) { g_aj[j0] = d0 + b1[j0]; g_aj[j1] = d1 + b1[j1]; }
    }

    // --- filter pass ---
    unsigned tkey = g_tkey;
    int i4 = blk * 256 + t;
    for (; i4 < N_MEM / 4; i4 += FILT_GRID * 256) {
        float4 v = ((const float4*)g_sims)[i4];
        int i = i4 * 4;
        if (mkey(v.x) >= tkey) { int p = atomicAdd(&g_ncand, 1); if (p < CAP) { g_cv[p] = v.x; g_ci[p] = i; } }
        if (mkey(v.y) >= tkey) { int p = atomicAdd(&g_ncand, 1); if (p < CAP) { g_cv[p] = v.y; g_ci[p] = i + 1; } }
        if (mkey(v.z) >= tkey) { int p = atomicAdd(&g_ncand, 1); if (p < CAP) { g_cv[p] = v.z; g_ci[p] = i + 2; } }
        if (mkey(v.w) >= tkey) { int p = atomicAdd(&g_ncand, 1); if (p < CAP) { g_cv[p] = v.w; g_ci[p] = i + 3; } }
    }
    if (t == 0) {
        __threadfence();
        is_last = (atomicAdd(&g_tick2, 1) == FILT_GRID - 1);
    }
    __syncthreads();
    if (!is_last) return;

    // --- select epilogue (only last block): copy survivors to smem once ---
    int n = g_ncand; if (n > CAP) n = CAP;
    for (int i = t; i < n; i += 256) { sv[i] = g_cv[i]; si[i] = g_ci[i]; }
    __syncthreads();
    if (w == 0) {
        for (int r = 0; r < 32; r++) {
            float bv = -1e30f; int bi = 0x7fffffff, bp = -1;
            for (int i = lane; i < n; i += 32) {
                float v = sv[i]; int idx = si[i];
                if (v > bv || (v == bv && idx < bi)) { bv = v; bi = idx; bp = i; }
            }
#pragma unroll
            for (int o = 16; o; o >>= 1) {
                float ov = __shfl_xor_sync(0xffffffffu, bv, o);
                int oi = __shfl_xor_sync(0xffffffffu, bi, o);
                int op = __shfl_xor_sync(0xffffffffu, bp, o);
                if (ov > bv || (ov == bv && oi < bi)) { bv = ov; bi = oi; bp = op; }
            }
            if (lane == 0) {
                g_cand[r] = bi;
                if (bp >= 0) sv[bp] = -1e30f;
            }
            __syncwarp();
        }
    }
}

// ---------------------------------------------------------------------------
// 4) rerank: score[c] = b2 + sum_j relu(a_j + dot(cand_c, W1[j,512:])) * W2[j]
//    32 blocks x 512 thr. LAST block runs the final top-16 and writes d_out.
__global__ void __launch_bounds__(512) k_rerank(const float* __restrict__ mem,
                                                const float* __restrict__ W1,
                                                const float* __restrict__ W2,
                                                const float* __restrict__ b2,
                                                float* __restrict__ out,
                                                int out_size) {
    __shared__ float4 cs[D_LAT / 4];
    __shared__ float wacc[16];
    __shared__ int is_last;
    int c = blockIdx.x, t = threadIdx.x;
    int cidx = g_cand[c];
    for (int i = t; i < D_LAT / 4; i += 512)
        cs[i] = ((const float4*)(mem + (size_t)cidx * D_LAT))[i];
    __syncthreads();
    int w = t >> 5, lane = t & 31;
    float acc = 0.f;
    for (int jj = 0; jj < 32; jj += 2) {
        int j0 = w * 32 + jj, j1 = j0 + 1;
        const float4* p0 = (const float4*)(W1 + (size_t)j0 * (2 * D_LAT) + D_LAT);
        const float4* p1 = (const float4*)(W1 + (size_t)j1 * (2 * D_LAT) + D_LAT);
        float d0 = 0.f, d1 = 0.f;
#pragma unroll
        for (int u = 0; u < 4; u++) {
            float4 a = p0[lane + 32 * u];
            float4 b = p1[lane + 32 * u];
            float4 q = cs[lane + 32 * u];
            d0 += a.x * q.x + a.y * q.y + a.z * q.z + a.w * q.w;
            d1 += b.x * q.x + b.y * q.y + b.z * q.z + b.w * q.w;
        }
        d0 = warp_sum(d0); d1 = warp_sum(d1);
        if (lane == 0) {
            float h0 = g_aj[j0] + d0; if (h0 > 0.f) acc += h0 * W2[j0];
            float h1 = g_aj[j1] + d1; if (h1 > 0.f) acc += h1 * W2[j1];
        }
    }
    if (lane == 0) wacc[w] = acc;
    __syncthreads();
    if (t == 0) {
        float s = 0.f;
        for (int i = 0; i < 16; i++) s += wacc[i];
        g_scores[c] = s + b2[0];
        __threadfence();
        is_last = (atomicAdd(&g_tick3, 1) == 31);
    }
    __syncthreads();
    if (!is_last) return;

    // --- final epilogue (only last block, thread 0) ---
    if (t == 0) {
        float sc[32]; int id[32];
        for (int i = 0; i < 32; i++) { sc[i] = g_scores[i]; id[i] = g_cand[i]; }
        for (int r = 0; r < 16; r++) {
            float bv = -1e30f; int bp = 0;
            for (int j = 0; j < 32; j++)
                if (sc[j] > bv) { bv = sc[j]; bp = j; }
            if (r < out_size)      out[r]      = bv;
            if (16 + r < out_size) out[16 + r] = (float)id[bp];
            sc[bp] = -1e30f;
        }
    }
}

// ---------------------------------------------------------------------------
extern "C" void kernel_launch(void* const* d_in, const int* in_sizes, int n_in,
                              void* d_out, int out_size) {
    const float* query  = (const float*)d_in[0];
    const float* memory = (const float*)d_in[1];
    const float* Wp     = (const float*)d_in[2];
    const float* bp     = (const float*)d_in[3];
    const float* W1     = (const float*)d_in[4];
    const float* b1     = (const float*)d_in[5];
    const float* W2     = (const float*)d_in[6];
    const float* b2     = (const float*)d_in[7];
    (void)in_sizes; (void)n_in;

    k_proj  <<<16, 512>>>(query, Wp, bp);
    k_sims  <<<SIMS_GRID, 256>>>(memory);
    k_filter<<<FILT_GRID, 256>>>(W1, b1);
    k_rerank<<<32, 512>>>(memory, W1, W2, b2, (float*)d_out, out_size);
}

// round 5
// speedup vs baseline: 2.2755x; 1.1456x over previous
#include <cuda_runtime.h>
#include <math.h>

#define N_MEM   500000
#define D_LAT   512
#define D_Q     768
#define NBINS   4096
#define CAP     1024
#define SIMS_GRID 592                       // 4 blocks/SM * 148
#define SIMS_WARPS (SIMS_GRID * 8)          // 4736
#define SIMS_STRIDE (SIMS_WARPS * 2)        // rows per grid-iteration
#define FILT_GRID 512
#define RER_GRID 256                        // 32 candidates x 8 j-chunks

__device__ __align__(16) float g_q[D_LAT];
__device__ float g_ss_part[16];
__device__ __align__(16) float g_aj[D_LAT];
__device__ __align__(16) float g_sims[N_MEM];
__device__ unsigned g_hist[NBINS];
__device__ unsigned g_tkey;
__device__ int g_ncand;
__device__ float g_cv[CAP];
__device__ int   g_ci[CAP];
__device__ int   g_cand[32];
__device__ float g_rpart[RER_GRID];
__device__ int g_tick1, g_tick2, g_tick3;

__device__ __forceinline__ float warp_sum(float v) {
#pragma unroll
    for (int o = 16; o; o >>= 1) v += __shfl_xor_sync(0xffffffffu, v, o);
    return v;
}

// monotonic float->uint key: order-preserving over all floats
__device__ __forceinline__ unsigned mkey(float f) {
    unsigned u = __float_as_uint(f);
    return (u & 0x80000000u) ? ~u : (u | 0x80000000u);
}

// ---------------------------------------------------------------------------
// 1) q = Wp @ query + bp (16 blocks x 512 thr, 2 rows/warp). Also resets
//    g_hist / counters for this replay (graph-replay safe).
__global__ void __launch_bounds__(512) k_proj(const float* __restrict__ query,
                                              const float* __restrict__ Wp,
                                              const float* __restrict__ bp) {
    __shared__ float4 qs[D_Q / 4];
    __shared__ float red[16];
    int t = threadIdx.x, blk = blockIdx.x;
    int gt = blk * 512 + t;
    if (gt < NBINS) g_hist[gt] = 0;
    if (gt == 0) { g_ncand = 0; g_tick1 = 0; g_tick2 = 0; g_tick3 = 0; }
    for (int i = t; i < D_Q / 4; i += 512) qs[i] = ((const float4*)query)[i];
    __syncthreads();
    int w = t >> 5, lane = t & 31;
    int r0 = blk * 32 + w * 2, r1 = r0 + 1;
    const float4* p0 = (const float4*)(Wp + (size_t)r0 * D_Q);
    const float4* p1 = (const float4*)(Wp + (size_t)r1 * D_Q);
    float d0 = 0.f, d1 = 0.f;
#pragma unroll
    for (int u = 0; u < 6; u++) {
        float4 a = p0[lane + 32 * u];
        float4 b = p1[lane + 32 * u];
        float4 q = qs[lane + 32 * u];
        d0 += a.x * q.x + a.y * q.y + a.z * q.z + a.w * q.w;
        d1 += b.x * q.x + b.y * q.y + b.z * q.z + b.w * q.w;
    }
    d0 = warp_sum(d0); d1 = warp_sum(d1);
    if (lane == 0) {
        float v0 = d0 + bp[r0], v1 = d1 + bp[r1];
        g_q[r0] = v0; g_q[r1] = v1;
        red[w] = v0 * v0 + v1 * v1;
    }
    __syncthreads();
    if (t == 0) {
        float s = 0.f;
        for (int i = 0; i < 16; i++) s += red[i];
        g_ss_part[blk] = s;
    }
}

// ---------------------------------------------------------------------------
// 2) sims[i] = dot(mem_i, qn)/(||mem_i||+1e-8). Persistent, 2 rows/warp/iter.
//    Fused smem histogram of monotonic keys. LAST block computes the
//    threshold key (warp-ballot suffix scan).
__global__ void __launch_bounds__(256, 4) k_sims(const float* __restrict__ mem) {
    __shared__ float4 qsh[D_LAT / 4];
    __shared__ unsigned hist[NBINS];
    __shared__ unsigned part[256];
    __shared__ int is_last;
    int t = threadIdx.x;
    float ss = 0.f;
#pragma unroll
    for (int i = 0; i < 16; i++) ss += g_ss_part[i];
    float inv = 1.0f / (sqrtf(ss) + 1e-8f);
    for (int i = t; i < D_LAT / 4; i += 256) {
        float4 q = ((const float4*)g_q)[i];
        q.x *= inv; q.y *= inv; q.z *= inv; q.w *= inv;
        qsh[i] = q;
    }
    for (int i = t; i < NBINS; i += 256) hist[i] = 0;
    __syncthreads();
    int w = t >> 5, lane = t & 31;
    int wg = blockIdx.x * 8 + w;
    for (int base = wg * 2; base < N_MEM; base += SIMS_STRIDE) {
        const float4* r0 = (const float4*)(mem + (size_t)base * D_LAT);
        const float4* r1 = (const float4*)(mem + (size_t)(base + 1) * D_LAT);
        float d0 = 0.f, s0 = 0.f, d1 = 0.f, s1 = 0.f;
#pragma unroll
        for (int u = 0; u < 4; u++) {
            float4 a = r0[lane + 32 * u];
            float4 b = r1[lane + 32 * u];
            float4 q = qsh[lane + 32 * u];
            d0 += a.x * q.x + a.y * q.y + a.z * q.z + a.w * q.w;
            s0 += a.x * a.x + a.y * a.y + a.z * a.z + a.w * a.w;
            d1 += b.x * q.x + b.y * q.y + b.z * q.z + b.w * q.w;
            s1 += b.x * b.x + b.y * b.y + b.z * b.z + b.w * b.w;
        }
        d0 = warp_sum(d0); s0 = warp_sum(s0);
        d1 = warp_sum(d1); s1 = warp_sum(s1);
        if (lane == 0) {
            float v0 = d0 / (sqrtf(s0) + 1e-8f);
            float v1 = d1 / (sqrtf(s1) + 1e-8f);
            g_sims[base] = v0;
            g_sims[base + 1] = v1;
            atomicAdd(&hist[mkey(v0) >> 20], 1u);
            atomicAdd(&hist[mkey(v1) >> 20], 1u);
        }
    }
    __syncthreads();
    for (int i = t; i < NBINS; i += 256) {
        unsigned c = hist[i];
        if (c) atomicAdd(&g_hist[i], c);
    }
    __syncthreads();
    if (t == 0) {
        __threadfence();
        is_last = (atomicAdd(&g_tick1, 1) == SIMS_GRID - 1);
    }
    __syncthreads();
    if (!is_last) return;

    // --- threshold epilogue (only last block) ---
    unsigned s16 = 0;
#pragma unroll
    for (int i = 0; i < 16; i++) s16 += g_hist[t * 16 + i];
    part[t] = s16;
    __syncthreads();
    if (w == 0) {
        unsigned c8 = 0;
#pragma unroll
        for (int i = 0; i < 8; i++) c8 += part[lane * 8 + i];
        unsigned suf = c8;
#pragma unroll
        for (int o = 1; o < 32; o <<= 1) {
            unsigned x = __shfl_down_sync(0xffffffffu, suf, o);
            if (lane + o < 32) suf += x;
        }
        unsigned above = __shfl_down_sync(0xffffffffu, suf, 1);
        if (lane == 31) above = 0;
        unsigned mask = __ballot_sync(0xffffffffu, suf >= 32u);
        int Lstar = 31 - __clz(mask);   // highest lane whose suffix >= 32
        if (lane == Lstar) {
            unsigned cum = above;
            int seg = Lstar * 8 + 7;
            for (; seg > Lstar * 8; seg--) {
                if (cum + part[seg] >= 32u) break;
                cum += part[seg];
            }
            int bin = seg * 16 + 15;
            for (; bin > seg * 16; bin--) {
                cum += g_hist[bin];
                if (cum >= 32u) break;
            }
            g_tkey = ((unsigned)bin) << 20;
        }
    }
}

// ---------------------------------------------------------------------------
// 3) filter + aj + select.
//    Blocks 0..31 first compute a_j (16 j's each). All blocks compact sims
//    with key >= threshold. LAST block runs the exact stable top-32 select
//    over an smem copy with a single warp (no global latency per round).
__global__ void __launch_bounds__(256) k_filter(const float* __restrict__ W1,
                                                const float* __restrict__ b1) {
    __shared__ float sv[CAP];
    __shared__ int   si[CAP];
    __shared__ float4 qsh[D_LAT / 4];
    __shared__ int is_last;
    int t = threadIdx.x, blk = blockIdx.x;
    int w = t >> 5, lane = t & 31;

    // --- aj sub-task on blocks 0..31 ---
    if (blk < 32) {
        for (int i = t; i < D_LAT / 4; i += 256) qsh[i] = ((const float4*)g_q)[i];
        __syncthreads();
        int j0 = blk * 16 + w * 2, j1 = j0 + 1;
        const float4* p0 = (const float4*)(W1 + (size_t)j0 * (2 * D_LAT));
        const float4* p1 = (const float4*)(W1 + (size_t)j1 * (2 * D_LAT));
        float d0 = 0.f, d1 = 0.f;
#pragma unroll
        for (int u = 0; u < 4; u++) {
            float4 a = p0[lane + 32 * u];
            float4 b = p1[lane + 32 * u];
            float4 q = qsh[lane + 32 * u];
            d0 += a.x * q.x + a.y * q.y + a.z * q.z + a.w * q.w;
            d1 += b.x * q.x + b.y * q.y + b.z * q.z + b.w * q.w;
        }
        d0 = warp_sum(d0); d1 = warp_sum(d1);
        if (lane == 0) { g_aj[j0] = d0 + b1[j0]; g_aj[j1] = d1 + b1[j1]; }
    }

    // --- filter pass ---
    unsigned tkey = g_tkey;
    int i4 = blk * 256 + t;
    for (; i4 < N_MEM / 4; i4 += FILT_GRID * 256) {
        float4 v = ((const float4*)g_sims)[i4];
        int i = i4 * 4;
        if (mkey(v.x) >= tkey) { int p = atomicAdd(&g_ncand, 1); if (p < CAP) { g_cv[p] = v.x; g_ci[p] = i; } }
        if (mkey(v.y) >= tkey) { int p = atomicAdd(&g_ncand, 1); if (p < CAP) { g_cv[p] = v.y; g_ci[p] = i + 1; } }
        if (mkey(v.z) >= tkey) { int p = atomicAdd(&g_ncand, 1); if (p < CAP) { g_cv[p] = v.z; g_ci[p] = i + 2; } }
        if (mkey(v.w) >= tkey) { int p = atomicAdd(&g_ncand, 1); if (p < CAP) { g_cv[p] = v.w; g_ci[p] = i + 3; } }
    }
    if (t == 0) {
        __threadfence();
        is_last = (atomicAdd(&g_tick2, 1) == FILT_GRID - 1);
    }
    __syncthreads();
    if (!is_last) return;

    // --- select epilogue (only last block): copy survivors to smem once ---
    int n = g_ncand; if (n > CAP) n = CAP;
    for (int i = t; i < n; i += 256) { sv[i] = g_cv[i]; si[i] = g_ci[i]; }
    __syncthreads();
    if (w == 0) {
        for (int r = 0; r < 32; r++) {
            float bv = -1e30f; int bi = 0x7fffffff, bp = -1;
            for (int i = lane; i < n; i += 32) {
                float v = sv[i]; int idx = si[i];
                if (v > bv || (v == bv && idx < bi)) { bv = v; bi = idx; bp = i; }
            }
#pragma unroll
            for (int o = 16; o; o >>= 1) {
                float ov = __shfl_xor_sync(0xffffffffu, bv, o);
                int oi = __shfl_xor_sync(0xffffffffu, bi, o);
                int op = __shfl_xor_sync(0xffffffffu, bp, o);
                if (ov > bv || (ov == bv && oi < bi)) { bv = ov; bi = oi; bp = op; }
            }
            if (lane == 0) {
                g_cand[r] = bi;
                if (bp >= 0) sv[bp] = -1e30f;
            }
            __syncwarp();
        }
    }
}

// ---------------------------------------------------------------------------
// 4) rerank, split over (candidate, j-chunk): block = c*8 + chunk, each block
//    computes partial = sum over its 64 j of relu(a_j + dot(cand_c, W1r_j))*W2[j].
//    16 warps x 4 j (2-way ILP x 2 iters). LAST block reduces the 8 partials
//    per candidate in fixed order, adds b2, and runs the final top-16.
__global__ void __launch_bounds__(512) k_rerank(const float* __restrict__ mem,
                                                const float* __restrict__ W1,
                                                const float* __restrict__ W2,
                                                const float* __restrict__ b2,
                                                float* __restrict__ out,
                                                int out_size) {
    __shared__ float4 cs[D_LAT / 4];
    __shared__ float wacc[16];
    __shared__ int is_last;
    int blk = blockIdx.x, t = threadIdx.x;
    int c = blk >> 3, chunk = blk & 7;
    int cidx = g_cand[c];
    for (int i = t; i < D_LAT / 4; i += 512)
        cs[i] = ((const float4*)(mem + (size_t)cidx * D_LAT))[i];
    __syncthreads();
    int w = t >> 5, lane = t & 31;
    float acc = 0.f;
#pragma unroll
    for (int jj = 0; jj < 4; jj += 2) {
        int j0 = chunk * 64 + w * 4 + jj, j1 = j0 + 1;
        const float4* p0 = (const float4*)(W1 + (size_t)j0 * (2 * D_LAT) + D_LAT);
        const float4* p1 = (const float4*)(W1 + (size_t)j1 * (2 * D_LAT) + D_LAT);
        float d0 = 0.f, d1 = 0.f;
#pragma unroll
        for (int u = 0; u < 4; u++) {
            float4 a = p0[lane + 32 * u];
            float4 b = p1[lane + 32 * u];
            float4 q = cs[lane + 32 * u];
            d0 += a.x * q.x + a.y * q.y + a.z * q.z + a.w * q.w;
            d1 += b.x * q.x + b.y * q.y + b.z * q.z + b.w * q.w;
        }
        d0 = warp_sum(d0); d1 = warp_sum(d1);
        if (lane == 0) {
            float h0 = g_aj[j0] + d0; if (h0 > 0.f) acc += h0 * W2[j0];
            float h1 = g_aj[j1] + d1; if (h1 > 0.f) acc += h1 * W2[j1];
        }
    }
    if (lane == 0) wacc[w] = acc;
    __syncthreads();
    if (t == 0) {
        float s = 0.f;
#pragma unroll
        for (int i = 0; i < 16; i++) s += wacc[i];
        g_rpart[blk] = s;
        __threadfence();
        is_last = (atomicAdd(&g_tick3, 1) == RER_GRID - 1);
    }
    __syncthreads();
    if (!is_last) return;

    // --- final epilogue (only last block): reduce partials + top-16 ---
    if (w == 0) {
        float sc;
        int id = 0;
        {
            float s = 0.f;
#pragma unroll
            for (int p = 0; p < 8; p++) s += g_rpart[lane * 8 + p];
            sc = s + b2[0];
            id = g_cand[lane];
        }
        // serial stable top-16 on lane 0 via shuffles
        if (lane == 0) { /* placeholder to keep structure */ }
        // gather all 32 (sc, id) onto lane 0 through smem
        __shared__ float fsc[32];
        __shared__ int   fid[32];
        fsc[lane] = sc; fid[lane] = id;
        __syncwarp();
        if (lane == 0) {
            for (int r = 0; r < 16; r++) {
                float bv = -1e30f; int bp = 0;
                for (int j = 0; j < 32; j++)
                    if (fsc[j] > bv) { bv = fsc[j]; bp = j; }
                if (r < out_size)      out[r]      = bv;
                if (16 + r < out_size) out[16 + r] = (float)fid[bp];
                fsc[bp] = -1e30f;
            }
        }
    }
}

// ---------------------------------------------------------------------------
extern "C" void kernel_launch(void* const* d_in, const int* in_sizes, int n_in,
                              void* d_out, int out_size) {
    const float* query  = (const float*)d_in[0];
    const float* memory = (const float*)d_in[1];
    const float* Wp     = (const float*)d_in[2];
    const float* bp     = (const float*)d_in[3];
    const float* W1     = (const float*)d_in[4];
    const float* b1     = (const float*)d_in[5];
    const float* W2     = (const float*)d_in[6];
    const float* b2     = (const float*)d_in[7];
    (void)in_sizes; (void)n_in;

    k_proj  <<<16, 512>>>(query, Wp, bp);
    k_sims  <<<SIMS_GRID, 256>>>(memory);
    k_filter<<<FILT_GRID, 256>>>(W1, b1);
    k_rerank<<<RER_GRID, 512>>>(memory, W1, W2, b2, (float*)d_out, out_size);
}